// round 15
// baseline (speedup 1.0000x reference)
#include <cuda_runtime.h>
#include <cuda_fp16.h>

#define NN 50000
#define EE 1600000
#define GG 16
#define HH 32
#define NEG_SLOPE 0.2f
#define NB 49   // scan blocks: ceil(50000/1024)

// ---------------- device scratch (static, no allocs) ----------------
__device__ __align__(128) __half2 g_xnh[NN * 16];   // fp16 node feats (gather target)
__device__ __align__(128) float g_out[NN * HH];     // fp32 layer output / next input
__device__ float g_u[NN];
__device__ float g_v[NN];
__device__ __align__(16) uint2 g_csr[EE];           // {src|et0h<<16, et1h|et2h<<16} grouped by dst
__device__ int   g_deg[NN];                         // zero-initialized; re-zeroed by pool each call
__device__ int   g_rowptr[NN + 1];
__device__ int   g_cursor[NN];
__device__ __align__(16) float g_w[3][8];
__device__ float g_d[3];
__device__ float g_pool[GG * HH];
__device__ float g_cnt[GG];
__device__ int   g_done;                            // pool completion counter (reset each call)

// ---------------- per-block dtype sniff: int64 ids have zero high halves ----------------
__device__ __forceinline__ int block_is64(const int* __restrict__ words) {
    __shared__ int sh_is64;
    if (threadIdx.x == 0) {
        int az = 1;
        for (int i = 0; i < 64; i++) {
            if (words[2 * i + 1] != 0) { az = 0; break; }
        }
        sh_is64 = az;
    }
    __syncthreads();
    return sh_is64;
}

// ---------------- deg histogram (4 edges/thread, no returns -> REDG) + prep (block 0) ----------------
__global__ void __launch_bounds__(256, 6)
deg_prep_kernel(const void* __restrict__ eidxv,
                const float* We1, const float* be1, const float* att1,
                const float* We2, const float* be2, const float* att2,
                const float* We3, const float* be3, const float* att3) {
    int is64 = block_is64((const int*)eidxv);

    if (blockIdx.x == 0) {
        __shared__ float M2[64], M3[64], c1[8], c2[8], c3[8];
        int t = threadIdx.x;
        if (t < 64) {
            int i = t >> 3, j = t & 7;
            float acc = 0.f;
            for (int k = 0; k < 8; k++) acc += We1[i * 8 + k] * We2[k * 8 + j];
            M2[t] = acc;
            if (i == 0) {
                float c = be2[j];
                for (int k = 0; k < 8; k++) c += be1[k] * We2[k * 8 + j];
                c2[j] = c;
                c1[j] = be1[j];
            }
        }
        __syncthreads();
        if (t < 64) {
            int i = t >> 3, j = t & 7;
            float acc3 = 0.f;
            for (int k = 0; k < 8; k++) acc3 += M2[i * 8 + k] * We3[k * 8 + j];
            M3[t] = acc3;
            if (i == 0) {
                float c = be3[j];
                for (int k = 0; k < 8; k++) c += c2[k] * We3[k * 8 + j];
                c3[j] = c;
            }
        }
        __syncthreads();
        if (t < 24) {
            int l = t >> 3, k = t & 7;
            const float* ae = (l == 0 ? att1 : (l == 1 ? att2 : att3)) + 64;
            float w = 0.f;
            for (int jj = 0; jj < 8; jj++) {
                float m = (l == 0) ? We1[k * 8 + jj] : (l == 1 ? M2[k * 8 + jj] : M3[k * 8 + jj]);
                w += m * ae[jj];
            }
            g_w[l][k] = w;
        }
        if (t < 3) {
            const float* ae = (t == 0 ? att1 : (t == 1 ? att2 : att3)) + 64;
            const float* c = (t == 0 ? c1 : (t == 1 ? c2 : c3));
            float d = 0.f;
            for (int jj = 0; jj < 8; jj++) d += c[jj] * ae[jj];
            g_d[t] = d;
        }
        for (int idx = t; idx < GG * HH; idx += blockDim.x) g_pool[idx] = 0.f;
        if (t < GG) g_cnt[t] = 0.f;
    }

    int t4 = blockIdx.x * blockDim.x + threadIdx.x;
    if (t4 * 4 >= EE) return;
    int d[4];
    if (is64) {
        const longlong4* p = (const longlong4*)((const long long*)eidxv + EE);
        longlong4 q = p[t4];
        d[0] = (int)q.x; d[1] = (int)q.y; d[2] = (int)q.z; d[3] = (int)q.w;
    } else {
        const int4* p = (const int4*)((const int*)eidxv + EE);
        int4 q = p[t4];
        d[0] = q.x; d[1] = q.y; d[2] = q.z; d[3] = q.w;
    }
#pragma unroll
    for (int i = 0; i < 4; i++) {
        int dn = min(max(d[i], 0), NN - 1);
        atomicAdd(&g_deg[dn], 1);   // result unused -> REDG
    }
}

// ---------------- fused scan: each block sums its deg-prefix, then local scan ----------------
__global__ void scan_kernel() {
    __shared__ int wsum[32];
    __shared__ int osum[32];
    __shared__ int sh_offset;
    int tid = threadIdx.x;
    int lane = tid & 31, wid = tid >> 5;
    // block offset: sum of g_deg[0 .. blockIdx.x*1024)
    int pre = blockIdx.x * 1024;
    int acc = 0;
    for (int i = tid; i < pre; i += 1024) acc += g_deg[i];
#pragma unroll
    for (int off = 16; off > 0; off >>= 1) acc += __shfl_down_sync(0xffffffffu, acc, off);
    if (lane == 0) osum[wid] = acc;
    __syncthreads();
    if (wid == 0) {
        int x = osum[lane];
#pragma unroll
        for (int off = 16; off > 0; off >>= 1) x += __shfl_down_sync(0xffffffffu, x, off);
        if (lane == 0) sh_offset = x;
    }
    // local inclusive scan over this block's 1024 deg entries
    int i = pre + tid;
    int v = (i < NN) ? g_deg[i] : 0;
    int incl = v;
#pragma unroll
    for (int off = 1; off < 32; off <<= 1) {
        int x = __shfl_up_sync(0xffffffffu, incl, off);
        if (lane >= off) incl += x;
    }
    if (lane == 31) wsum[wid] = incl;
    __syncthreads();
    if (wid == 0) {
        int x = wsum[lane];
        int xi = x;
#pragma unroll
        for (int off = 1; off < 32; off <<= 1) {
            int y = __shfl_up_sync(0xffffffffu, xi, off);
            if (lane >= off) xi += y;
        }
        wsum[lane] = xi - x;   // exclusive warp offsets
    }
    __syncthreads();
    int excl = incl - v + wsum[wid] + sh_offset;
    if (i < NN) { g_rowptr[i] = excl; g_cursor[i] = excl; }
    if (i == 0) g_rowptr[NN] = EE;
}

// ---------------- fused eterm + scatter: 2 edges/thread, cursor atomics ----------------
__global__ void __launch_bounds__(256, 6)
scatter_fused_kernel(const void* __restrict__ eidxv, const float* __restrict__ ea) {
    int is64 = block_is64((const int*)eidxv);
    int t = blockIdx.x * blockDim.x + threadIdx.x;
    if (t * 2 >= EE) return;
    int sn[2], dn[2];
    if (is64) {
        const longlong2* ps = (const longlong2*)eidxv;
        const longlong2* pd = (const longlong2*)((const long long*)eidxv + EE);
        longlong2 qs = ps[t], qd = pd[t];
        sn[0] = (int)qs.x; sn[1] = (int)qs.y;
        dn[0] = (int)qd.x; dn[1] = (int)qd.y;
    } else {
        const int2* ps = (const int2*)eidxv;
        const int2* pd = (const int2*)((const int*)eidxv + EE);
        int2 qs = ps[t], qd = pd[t];
        sn[0] = qs.x; sn[1] = qs.y;
        dn[0] = qd.x; dn[1] = qd.y;
    }
    const float4* ea4 = (const float4*)ea;
    uint2 pay[2];
#pragma unroll
    for (int k = 0; k < 2; k++) {
        int e = t * 2 + k;
        unsigned s = (unsigned)min(max(sn[k], 0), NN - 1);
        float4 a0 = ea4[e * 2];
        float4 a1 = ea4[e * 2 + 1];
        float et[3];
#pragma unroll
        for (int l = 0; l < 3; l++) {
            const float* w = g_w[l];
            et[l] = g_d[l]
                  + a0.x * w[0] + a0.y * w[1] + a0.z * w[2] + a0.w * w[3]
                  + a1.x * w[4] + a1.y * w[5] + a1.z * w[6] + a1.w * w[7];
        }
        unsigned h0 = (unsigned)__half_as_ushort(__float2half_rn(et[0]));
        unsigned h1 = (unsigned)__half_as_ushort(__float2half_rn(et[1]));
        unsigned h2 = (unsigned)__half_as_ushort(__float2half_rn(et[2]));
        pay[k].x = s | (h0 << 16);
        pay[k].y = h1 | (h2 << 16);
    }
    int pos[2];
#pragma unroll
    for (int k = 0; k < 2; k++) {
        int d = min(max(dn[k], 0), NN - 1);
        pos[k] = atomicAdd(&g_cursor[d], 1);
    }
#pragma unroll
    for (int k = 0; k < 2; k++) g_csr[pos[k]] = pay[k];
}

// ---------------- node linear: smem-staged input, fp16 xn output ----------------
template <int IN, bool RELU, bool FROM_GOUT>
__global__ void node_linear_kernel(const float* __restrict__ xin_ext,
                                   const float* __restrict__ W,
                                   const float* __restrict__ b,
                                   const float* __restrict__ att) {
    __shared__ float sW[IN * HH];
    __shared__ float sb[HH];
    __shared__ float sA[64];
    __shared__ float sX[256 * (IN + 1)];
    int tid = threadIdx.x;
    for (int i = tid; i < IN * HH; i += blockDim.x) sW[i] = W[i];
    if (tid < HH) sb[tid] = b[tid];
    if (tid < 64) sA[tid] = att[tid];
    int base = blockIdx.x * 256;
    int nvalid = min(256, NN - base);
    const float* src = FROM_GOUT ? g_out : xin_ext;
    for (int i = tid; i < nvalid * IN; i += 256) {
        int nl = i / IN;
        int k = i - nl * IN;
        sX[nl * (IN + 1) + k] = src[(size_t)base * IN + i];
    }
    __syncthreads();
    int node = base + tid;
    if (tid >= nvalid) return;
    const float* xr = sX + tid * (IN + 1);
    float acc[HH];
#pragma unroll
    for (int h = 0; h < HH; h++) acc[h] = sb[h];
#pragma unroll
    for (int k = 0; k < IN; k++) {
        float xv = xr[k];
        if (RELU) xv = fmaxf(xv, 0.f);
#pragma unroll
        for (int h = 0; h < HH; h++) acc[h] = fmaf(xv, sW[k * HH + h], acc[h]);
    }
    uint4* o = (uint4*)(g_xnh + (size_t)node * 16);
#pragma unroll
    for (int q = 0; q < 4; q++) {
        uint4 pk;
        __half2 h0 = __floats2half2_rn(acc[8 * q + 0], acc[8 * q + 1]);
        __half2 h1 = __floats2half2_rn(acc[8 * q + 2], acc[8 * q + 3]);
        __half2 h2 = __floats2half2_rn(acc[8 * q + 4], acc[8 * q + 5]);
        __half2 h3 = __floats2half2_rn(acc[8 * q + 6], acc[8 * q + 7]);
        pk.x = *(unsigned*)&h0; pk.y = *(unsigned*)&h1;
        pk.z = *(unsigned*)&h2; pk.w = *(unsigned*)&h3;
        o[q] = pk;
    }
    float u = 0.f, v = 0.f;
#pragma unroll
    for (int h = 0; h < HH; h++) {
        u = fmaf(acc[h], sA[h], u);
        v = fmaf(acc[h], sA[h + 32], v);
    }
    g_u[node] = u;
    g_v[node] = v;
}

// ---------------- fused softmax + aggregate: one warp per dst node ----------------
// Phase 1: 32 lanes compute p for 32 edges, stage {sn,p} in smem.
// Phase 2: 4-deep prefetch — load all 4 row-slices per 4-lane group, then FMA.
template <int L>
__global__ void edge_fused_kernel() {
    __shared__ __align__(8) float2 sE[8][32];
    int wib = threadIdx.x >> 5;
    int w = (blockIdx.x * blockDim.x + threadIdx.x) >> 5;
    int lane = threadIdx.x & 31;
    if (w >= NN) return;
    int start = g_rowptr[w];
    int end = g_rowptr[w + 1];
    float u = g_u[w];
    int part = lane & 3, grp = lane >> 2;
    float acc[8] = {0.f, 0.f, 0.f, 0.f, 0.f, 0.f, 0.f, 0.f};
    float s = 0.f;
    for (int base = start; base < end; base += 32) {
        int e = base + lane;
        float p = 0.f; int sn = 0;
        if (e < end) {
            uint2 q = g_csr[e];
            sn = (int)(q.x & 0xffffu);
            unsigned hb = (L == 0) ? (q.x >> 16) : (L == 1) ? (q.y & 0xffffu) : (q.y >> 16);
            float et = __half2float(__ushort_as_half((unsigned short)hb));
            float lg = u + g_v[sn] + et;
            lg = (lg > 0.f) ? lg : NEG_SLOPE * lg;
            p = __expf(lg);
        }
        sE[wib][lane] = make_float2(__int_as_float(sn), p);
        __syncwarp();
        int cnt = min(32, end - base);
        float pj[4];
        uint4 rvj[4];
#pragma unroll
        for (int it = 0; it < 4; it++) {
            int j = grp + it * 8;
            if (j < cnt) {
                float2 sp = sE[wib][j];
                pj[it] = sp.y;
                rvj[it] = ((const uint4*)(g_xnh + (size_t)__float_as_int(sp.x) * 16))[part];
            } else {
                pj[it] = 0.f;
                rvj[it] = make_uint4(0u, 0u, 0u, 0u);
            }
        }
#pragma unroll
        for (int it = 0; it < 4; it++) {
            float pp = pj[it];
            uint4 rv = rvj[it];
            float2 f0 = __half22float2(*(__half2*)&rv.x);
            float2 f1 = __half22float2(*(__half2*)&rv.y);
            float2 f2 = __half22float2(*(__half2*)&rv.z);
            float2 f3 = __half22float2(*(__half2*)&rv.w);
            acc[0] = fmaf(pp, f0.x, acc[0]);
            acc[1] = fmaf(pp, f0.y, acc[1]);
            acc[2] = fmaf(pp, f1.x, acc[2]);
            acc[3] = fmaf(pp, f1.y, acc[3]);
            acc[4] = fmaf(pp, f2.x, acc[4]);
            acc[5] = fmaf(pp, f2.y, acc[5]);
            acc[6] = fmaf(pp, f3.x, acc[6]);
            acc[7] = fmaf(pp, f3.y, acc[7]);
            s += pp;
        }
        __syncwarp();
    }
#pragma unroll
    for (int off = 16; off >= 4; off >>= 1) {
#pragma unroll
        for (int i = 0; i < 8; i++) acc[i] += __shfl_down_sync(0xffffffffu, acc[i], off);
        s += __shfl_down_sync(0xffffffffu, s, off);
    }
    if (grp == 0) {
        float inv = 1.f / (s + 1e-16f);
        float4* o = (float4*)(g_out + (size_t)w * HH);
        o[part * 2]     = make_float4(acc[0] * inv, acc[1] * inv, acc[2] * inv, acc[3] * inv);
        o[part * 2 + 1] = make_float4(acc[4] * inv, acc[5] * inv, acc[6] * inv, acc[7] * inv);
    }
}

// ---------------- fused pool + head (last block runs head); re-zero g_deg ----------------
__global__ void pool_head_kernel(const void* __restrict__ batchv,
                                 const int* __restrict__ eidx_words,
                                 const float* __restrict__ Wlin,
                                 const float* __restrict__ blin,
                                 float* __restrict__ out) {
    int is64 = block_is64(eidx_words);
    int gtid = blockIdx.x * blockDim.x + threadIdx.x;
    if (gtid < NN) g_deg[gtid] = 0;
    int w = gtid >> 5;
    int lane = threadIdx.x & 31;
    int base = w * 32;
    if (base < NN) {
        int nmax = min(32, NN - base);
        int myb = 0;
        if (lane < nmax) {
            if (is64) myb = (int)((const long long*)batchv)[base + lane];
            else      myb = ((const int*)batchv)[base + lane];
            myb = min(max(myb, 0), GG - 1);
        }
        float acc = 0.f, cnt = 0.f;
        int curb = __shfl_sync(0xffffffffu, myb, 0);
        for (int n = 0; n < nmax; n++) {
            int b = __shfl_sync(0xffffffffu, myb, n);
            if (b != curb) {
                atomicAdd(&g_pool[curb * HH + lane], acc);
                if (lane == 0) atomicAdd(&g_cnt[curb], cnt);
                acc = 0.f; cnt = 0.f; curb = b;
            }
            acc += g_out[(size_t)(base + n) * HH + lane];
            cnt += 1.f;
        }
        atomicAdd(&g_pool[curb * HH + lane], acc);
        if (lane == 0) atomicAdd(&g_cnt[curb], cnt);
    }
    // completion: last block computes the head
    __shared__ int sh_last;
    __threadfence();
    __syncthreads();
    if (threadIdx.x == 0) {
        int old = atomicAdd(&g_done, 1);
        sh_last = (old == (int)gridDim.x - 1);
    }
    __syncthreads();
    if (sh_last) {
        int tid = threadIdx.x;
        int g0 = tid >> 5;   // 0..7
#pragma unroll
        for (int rep = 0; rep < 2; rep++) {
            int g = g0 + rep * 8;
            float v = g_pool[g * HH + lane] * Wlin[lane];
#pragma unroll
            for (int o = 16; o > 0; o >>= 1) v += __shfl_xor_sync(0xffffffffu, v, o);
            if (lane == 0) out[g] = v / fmaxf(g_cnt[g], 1.f) + blin[0];
        }
        if (tid == 0) g_done = 0;   // reset for next (graph-replayed) call
    }
}

// ---------------- launch ----------------
extern "C" void kernel_launch(void* const* d_in, const int* in_sizes, int n_in,
                              void* d_out, int out_size) {
    const float* x     = (const float*)d_in[0];
    const float* ea    = (const float*)d_in[1];
    const void*  eidx  = d_in[2];
    const void*  batch = d_in[3];
    const float *Wn1 = (const float*)d_in[4],  *bn1 = (const float*)d_in[5];
    const float *We1 = (const float*)d_in[6],  *be1 = (const float*)d_in[7],  *att1 = (const float*)d_in[8];
    const float *Wn2 = (const float*)d_in[9],  *bn2 = (const float*)d_in[10];
    const float *We2 = (const float*)d_in[11], *be2 = (const float*)d_in[12], *att2 = (const float*)d_in[13];
    const float *Wn3 = (const float*)d_in[14], *bn3 = (const float*)d_in[15];
    const float *We3 = (const float*)d_in[16], *be3 = (const float*)d_in[17], *att3 = (const float*)d_in[18];
    const float *Wlin = (const float*)d_in[19], *blin = (const float*)d_in[20];
    float* out = (float*)d_out;

    const int NODE_BLOCKS = (NN + 255) / 256;
    const int WARP_BLOCKS = (NN * 32 + 255) / 256;

    deg_prep_kernel<<<(EE / 4 + 255) / 256, 256>>>(eidx,
        We1, be1, att1, We2, be2, att2, We3, be3, att3);
    scan_kernel<<<NB, 1024>>>();
    scatter_fused_kernel<<<(EE / 2 + 255) / 256, 256>>>(eidx, ea);

    // layer 1
    node_linear_kernel<16, false, false><<<NODE_BLOCKS, 256>>>(x, Wn1, bn1, att1);
    edge_fused_kernel<0><<<WARP_BLOCKS, 256>>>();
    // layer 2
    node_linear_kernel<32, true, true><<<NODE_BLOCKS, 256>>>(nullptr, Wn2, bn2, att2);
    edge_fused_kernel<1><<<WARP_BLOCKS, 256>>>();
    // layer 3
    node_linear_kernel<32, true, true><<<NODE_BLOCKS, 256>>>(nullptr, Wn3, bn3, att3);
    edge_fused_kernel<2><<<WARP_BLOCKS, 256>>>();

    // fused pooling + head
    pool_head_kernel<<<NODE_BLOCKS, 256>>>(batch, (const int*)eidx, Wlin, blin, out);
}

// round 16
// speedup vs baseline: 1.0469x; 1.0469x over previous
#include <cuda_runtime.h>
#include <cuda_fp16.h>

#define NN 50000
#define EE 1600000
#define GG 16
#define HH 32
#define NEG_SLOPE 0.2f
#define NB 49   // scan blocks: ceil(50000/1024)

// ---------------- device scratch (static, no allocs) ----------------
__device__ __align__(128) __half2 g_xnh[NN * 16];   // fp16 node feats (gather target)
__device__ __align__(128) float g_out[NN * HH];     // fp32 layer output / next input
__device__ float g_u[NN];
__device__ float g_v[NN];
__device__ __align__(16) uint2 g_csr[EE];           // {src|et0h<<16, et1h|et2h<<16} grouped by dst
__device__ int   g_deg[NN];                         // zero-initialized; re-zeroed by pool each call
__device__ int   g_rowptr[NN + 1];
__device__ int   g_cursor[NN];
__device__ int   g_bsum[NB];
__device__ __align__(16) float g_w[3][8];
__device__ float g_d[3];
__device__ float g_pool[GG * HH];
__device__ float g_cnt[GG];

// ---------------- per-block dtype sniff: int64 ids have zero high halves ----------------
__device__ __forceinline__ int block_is64(const int* __restrict__ words) {
    __shared__ int sh_is64;
    if (threadIdx.x == 0) {
        int az = 1;
        for (int i = 0; i < 64; i++) {
            if (words[2 * i + 1] != 0) { az = 0; break; }
        }
        sh_is64 = az;
    }
    __syncthreads();
    return sh_is64;
}

// ---------------- deg histogram (4 edges/thread, fire-and-forget REDG) + prep (block 0) ----------------
__global__ void __launch_bounds__(256, 6)
deg_prep_kernel(const void* __restrict__ eidxv,
                const float* We1, const float* be1, const float* att1,
                const float* We2, const float* be2, const float* att2,
                const float* We3, const float* be3, const float* att3) {
    int is64 = block_is64((const int*)eidxv);

    if (blockIdx.x == 0) {
        __shared__ float M2[64], M3[64], c1[8], c2[8], c3[8];
        int t = threadIdx.x;
        if (t < 64) {
            int i = t >> 3, j = t & 7;
            float acc = 0.f;
            for (int k = 0; k < 8; k++) acc += We1[i * 8 + k] * We2[k * 8 + j];
            M2[t] = acc;
            if (i == 0) {
                float c = be2[j];
                for (int k = 0; k < 8; k++) c += be1[k] * We2[k * 8 + j];
                c2[j] = c;
                c1[j] = be1[j];
            }
        }
        __syncthreads();
        if (t < 64) {
            int i = t >> 3, j = t & 7;
            float acc3 = 0.f;
            for (int k = 0; k < 8; k++) acc3 += M2[i * 8 + k] * We3[k * 8 + j];
            M3[t] = acc3;
            if (i == 0) {
                float c = be3[j];
                for (int k = 0; k < 8; k++) c += c2[k] * We3[k * 8 + j];
                c3[j] = c;
            }
        }
        __syncthreads();
        if (t < 24) {
            int l = t >> 3, k = t & 7;
            const float* ae = (l == 0 ? att1 : (l == 1 ? att2 : att3)) + 64;
            float w = 0.f;
            for (int jj = 0; jj < 8; jj++) {
                float m = (l == 0) ? We1[k * 8 + jj] : (l == 1 ? M2[k * 8 + jj] : M3[k * 8 + jj]);
                w += m * ae[jj];
            }
            g_w[l][k] = w;
        }
        if (t < 3) {
            const float* ae = (t == 0 ? att1 : (t == 1 ? att2 : att3)) + 64;
            const float* c = (t == 0 ? c1 : (t == 1 ? c2 : c3));
            float d = 0.f;
            for (int jj = 0; jj < 8; jj++) d += c[jj] * ae[jj];
            g_d[t] = d;
        }
        for (int idx = t; idx < GG * HH; idx += blockDim.x) g_pool[idx] = 0.f;
        if (t < GG) g_cnt[t] = 0.f;
    }

    int t4 = blockIdx.x * blockDim.x + threadIdx.x;
    if (t4 * 4 >= EE) return;
    int d[4];
    if (is64) {
        const longlong4* p = (const longlong4*)((const long long*)eidxv + EE);
        longlong4 q = p[t4];
        d[0] = (int)q.x; d[1] = (int)q.y; d[2] = (int)q.z; d[3] = (int)q.w;
    } else {
        const int4* p = (const int4*)((const int*)eidxv + EE);
        int4 q = p[t4];
        d[0] = q.x; d[1] = q.y; d[2] = q.z; d[3] = q.w;
    }
#pragma unroll
    for (int i = 0; i < 4; i++) {
        int dn = min(max(d[i], 0), NN - 1);
        atomicAdd(&g_deg[dn], 1);   // result unused -> REDG
    }
}

// ---------------- scanA: per-1024-chunk sums ----------------
__global__ void scanA_kernel() {
    __shared__ int sh[32];
    int i = blockIdx.x * 1024 + threadIdx.x;
    int v = (i < NN) ? g_deg[i] : 0;
#pragma unroll
    for (int off = 16; off > 0; off >>= 1) v += __shfl_down_sync(0xffffffffu, v, off);
    if ((threadIdx.x & 31) == 0) sh[threadIdx.x >> 5] = v;
    __syncthreads();
    if (threadIdx.x < 32) {
        int x = sh[threadIdx.x];
#pragma unroll
        for (int off = 16; off > 0; off >>= 1) x += __shfl_down_sync(0xffffffffu, x, off);
        if (threadIdx.x == 0) g_bsum[blockIdx.x] = x;
    }
}

// ---------------- scanC: local scan + inline block-offset reduction ----------------
__global__ void scanC_kernel() {
    __shared__ int wsum[32];
    __shared__ int sred[2];
    int tid = threadIdx.x;
    int lane = tid & 31, wid = tid >> 5;
    if (tid < 64) {
        int v = (tid < blockIdx.x && tid < NB) ? g_bsum[tid] : 0;
#pragma unroll
        for (int off = 16; off > 0; off >>= 1) v += __shfl_down_sync(0xffffffffu, v, off);
        if ((tid & 31) == 0) sred[tid >> 5] = v;
    }
    int i = blockIdx.x * 1024 + tid;
    int v = (i < NN) ? g_deg[i] : 0;
    int incl = v;
#pragma unroll
    for (int off = 1; off < 32; off <<= 1) {
        int x = __shfl_up_sync(0xffffffffu, incl, off);
        if (lane >= off) incl += x;
    }
    if (lane == 31) wsum[wid] = incl;
    __syncthreads();
    if (wid == 0) {
        int x = wsum[lane];
        int xi = x;
#pragma unroll
        for (int off = 1; off < 32; off <<= 1) {
            int y = __shfl_up_sync(0xffffffffu, xi, off);
            if (lane >= off) xi += y;
        }
        wsum[lane] = xi - x;
    }
    __syncthreads();
    int excl = incl - v + wsum[wid] + sred[0] + sred[1];
    if (i < NN) { g_rowptr[i] = excl; g_cursor[i] = excl; }
    if (i == 0) g_rowptr[NN] = EE;
}

// ---------------- fused eterm + scatter: 2 edges/thread, cursor atomics ----------------
__global__ void __launch_bounds__(256, 6)
scatter_fused_kernel(const void* __restrict__ eidxv, const float* __restrict__ ea) {
    int is64 = block_is64((const int*)eidxv);
    int t = blockIdx.x * blockDim.x + threadIdx.x;
    if (t * 2 >= EE) return;
    int sn[2], dn[2];
    if (is64) {
        const longlong2* ps = (const longlong2*)eidxv;
        const longlong2* pd = (const longlong2*)((const long long*)eidxv + EE);
        longlong2 qs = ps[t], qd = pd[t];
        sn[0] = (int)qs.x; sn[1] = (int)qs.y;
        dn[0] = (int)qd.x; dn[1] = (int)qd.y;
    } else {
        const int2* ps = (const int2*)eidxv;
        const int2* pd = (const int2*)((const int*)eidxv + EE);
        int2 qs = ps[t], qd = pd[t];
        sn[0] = qs.x; sn[1] = qs.y;
        dn[0] = qd.x; dn[1] = qd.y;
    }
    const float4* ea4 = (const float4*)ea;
    uint2 pay[2];
#pragma unroll
    for (int k = 0; k < 2; k++) {
        int e = t * 2 + k;
        unsigned s = (unsigned)min(max(sn[k], 0), NN - 1);
        float4 a0 = ea4[e * 2];
        float4 a1 = ea4[e * 2 + 1];
        float et[3];
#pragma unroll
        for (int l = 0; l < 3; l++) {
            const float* w = g_w[l];
            et[l] = g_d[l]
                  + a0.x * w[0] + a0.y * w[1] + a0.z * w[2] + a0.w * w[3]
                  + a1.x * w[4] + a1.y * w[5] + a1.z * w[6] + a1.w * w[7];
        }
        unsigned h0 = (unsigned)__half_as_ushort(__float2half_rn(et[0]));
        unsigned h1 = (unsigned)__half_as_ushort(__float2half_rn(et[1]));
        unsigned h2 = (unsigned)__half_as_ushort(__float2half_rn(et[2]));
        pay[k].x = s | (h0 << 16);
        pay[k].y = h1 | (h2 << 16);
    }
    int pos[2];
#pragma unroll
    for (int k = 0; k < 2; k++) {
        int d = min(max(dn[k], 0), NN - 1);
        pos[k] = atomicAdd(&g_cursor[d], 1);
    }
#pragma unroll
    for (int k = 0; k < 2; k++) g_csr[pos[k]] = pay[k];
}

// ---------------- node linear: 4 threads per node (64 nodes / 256-thread block) ----------------
// Each thread computes 8 of the 32 outputs for its node; u/v via 4-lane shuffle reduce.
template <int IN, bool RELU, bool FROM_GOUT>
__global__ void __launch_bounds__(256, 6)
node_linear_kernel(const float* __restrict__ xin_ext,
                   const float* __restrict__ W,
                   const float* __restrict__ b,
                   const float* __restrict__ att) {
    __shared__ float sW[IN * HH];
    __shared__ float sb[HH];
    __shared__ float sA[64];
    __shared__ float sX[64 * (IN + 1)];
    int tid = threadIdx.x;
    for (int i = tid; i < IN * HH; i += 256) sW[i] = W[i];
    if (tid < HH) sb[tid] = b[tid];
    if (tid < 64) sA[tid] = att[tid];
    int base = blockIdx.x * 64;
    int nvalid = min(64, NN - base);
    const float* src = FROM_GOUT ? g_out : xin_ext;
    // coalesced stage of 64 rows; ReLU applied here
    for (int i = tid; i < nvalid * IN; i += 256) {
        int nl = i / IN;
        int k = i - nl * IN;
        float xv = src[(size_t)base * IN + i];
        if (RELU) xv = fmaxf(xv, 0.f);
        sX[nl * (IN + 1) + k] = xv;
    }
    __syncthreads();
    int nl = tid >> 2;            // node within block
    int part = tid & 3;           // output slice [part*8, part*8+8)
    int node = base + nl;
    if (nl >= nvalid) return;
    const float* xr = sX + nl * (IN + 1);
    const float* wp = sW + part * 8;
    float acc[8];
#pragma unroll
    for (int h = 0; h < 8; h++) acc[h] = sb[part * 8 + h];
#pragma unroll
    for (int k = 0; k < IN; k++) {
        float xv = xr[k];
#pragma unroll
        for (int h = 0; h < 8; h++) acc[h] = fmaf(xv, wp[k * HH + h], acc[h]);
    }
    // pack 8 outputs -> one 16B store (4 threads cover the 64B fp16 row)
    uint4 pk;
    __half2 h0 = __floats2half2_rn(acc[0], acc[1]);
    __half2 h1 = __floats2half2_rn(acc[2], acc[3]);
    __half2 h2 = __floats2half2_rn(acc[4], acc[5]);
    __half2 h3 = __floats2half2_rn(acc[6], acc[7]);
    pk.x = *(unsigned*)&h0; pk.y = *(unsigned*)&h1;
    pk.z = *(unsigned*)&h2; pk.w = *(unsigned*)&h3;
    ((uint4*)(g_xnh + (size_t)node * 16))[part] = pk;
    // u/v partials over this slice, then 4-lane reduction
    float u = 0.f, v = 0.f;
#pragma unroll
    for (int h = 0; h < 8; h++) {
        u = fmaf(acc[h], sA[part * 8 + h], u);
        v = fmaf(acc[h], sA[32 + part * 8 + h], v);
    }
    u += __shfl_xor_sync(0xffffffffu, u, 1);
    u += __shfl_xor_sync(0xffffffffu, u, 2);
    v += __shfl_xor_sync(0xffffffffu, v, 1);
    v += __shfl_xor_sync(0xffffffffu, v, 2);
    if (part == 0) {
        g_u[node] = u;
        g_v[node] = v;
    }
}

// ---------------- fused softmax + aggregate: one warp per dst node ----------------
// Phase 1: 32 lanes compute p for 32 edges, stage {sn,p} in smem.
// Phase 2: 4-deep prefetch — load all 4 row-slices per 4-lane group, then FMA.
template <int L>
__global__ void edge_fused_kernel() {
    __shared__ __align__(8) float2 sE[8][32];
    int wib = threadIdx.x >> 5;
    int w = (blockIdx.x * blockDim.x + threadIdx.x) >> 5;
    int lane = threadIdx.x & 31;
    if (w >= NN) return;
    int start = g_rowptr[w];
    int end = g_rowptr[w + 1];
    float u = g_u[w];
    int part = lane & 3, grp = lane >> 2;
    float acc[8] = {0.f, 0.f, 0.f, 0.f, 0.f, 0.f, 0.f, 0.f};
    float s = 0.f;
    for (int base = start; base < end; base += 32) {
        int e = base + lane;
        float p = 0.f; int sn = 0;
        if (e < end) {
            uint2 q = g_csr[e];
            sn = (int)(q.x & 0xffffu);
            unsigned hb = (L == 0) ? (q.x >> 16) : (L == 1) ? (q.y & 0xffffu) : (q.y >> 16);
            float et = __half2float(__ushort_as_half((unsigned short)hb));
            float lg = u + g_v[sn] + et;
            lg = (lg > 0.f) ? lg : NEG_SLOPE * lg;
            p = __expf(lg);
        }
        sE[wib][lane] = make_float2(__int_as_float(sn), p);
        __syncwarp();
        int cnt = min(32, end - base);
        float pj[4];
        uint4 rvj[4];
#pragma unroll
        for (int it = 0; it < 4; it++) {
            int j = grp + it * 8;
            if (j < cnt) {
                float2 sp = sE[wib][j];
                pj[it] = sp.y;
                rvj[it] = ((const uint4*)(g_xnh + (size_t)__float_as_int(sp.x) * 16))[part];
            } else {
                pj[it] = 0.f;
                rvj[it] = make_uint4(0u, 0u, 0u, 0u);
            }
        }
#pragma unroll
        for (int it = 0; it < 4; it++) {
            float pp = pj[it];
            uint4 rv = rvj[it];
            float2 f0 = __half22float2(*(__half2*)&rv.x);
            float2 f1 = __half22float2(*(__half2*)&rv.y);
            float2 f2 = __half22float2(*(__half2*)&rv.z);
            float2 f3 = __half22float2(*(__half2*)&rv.w);
            acc[0] = fmaf(pp, f0.x, acc[0]);
            acc[1] = fmaf(pp, f0.y, acc[1]);
            acc[2] = fmaf(pp, f1.x, acc[2]);
            acc[3] = fmaf(pp, f1.y, acc[3]);
            acc[4] = fmaf(pp, f2.x, acc[4]);
            acc[5] = fmaf(pp, f2.y, acc[5]);
            acc[6] = fmaf(pp, f3.x, acc[6]);
            acc[7] = fmaf(pp, f3.y, acc[7]);
            s += pp;
        }
        __syncwarp();
    }
#pragma unroll
    for (int off = 16; off >= 4; off >>= 1) {
#pragma unroll
        for (int i = 0; i < 8; i++) acc[i] += __shfl_down_sync(0xffffffffu, acc[i], off);
        s += __shfl_down_sync(0xffffffffu, s, off);
    }
    if (grp == 0) {
        float inv = 1.f / (s + 1e-16f);
        float4* o = (float4*)(g_out + (size_t)w * HH);
        o[part * 2]     = make_float4(acc[0] * inv, acc[1] * inv, acc[2] * inv, acc[3] * inv);
        o[part * 2 + 1] = make_float4(acc[4] * inv, acc[5] * inv, acc[6] * inv, acc[7] * inv);
    }
}

// ---------------- mean pool over sorted batch; re-zero g_deg for next call ----------------
__global__ void pool_kernel(const void* __restrict__ batchv, const int* __restrict__ eidx_words) {
    int is64 = block_is64(eidx_words);
    int gtid = blockIdx.x * blockDim.x + threadIdx.x;
    if (gtid < NN) g_deg[gtid] = 0;
    int w = gtid >> 5;
    int lane = threadIdx.x & 31;
    int base = w * 32;
    if (base >= NN) return;
    int nmax = min(32, NN - base);
    int myb = 0;
    if (lane < nmax) {
        if (is64) myb = (int)((const long long*)batchv)[base + lane];
        else      myb = ((const int*)batchv)[base + lane];
        myb = min(max(myb, 0), GG - 1);
    }
    float acc = 0.f, cnt = 0.f;
    int curb = __shfl_sync(0xffffffffu, myb, 0);
    for (int n = 0; n < nmax; n++) {
        int b = __shfl_sync(0xffffffffu, myb, n);
        if (b != curb) {
            atomicAdd(&g_pool[curb * HH + lane], acc);
            if (lane == 0) atomicAdd(&g_cnt[curb], cnt);
            acc = 0.f; cnt = 0.f; curb = b;
        }
        acc += g_out[(size_t)(base + n) * HH + lane];
        cnt += 1.f;
    }
    atomicAdd(&g_pool[curb * HH + lane], acc);
    if (lane == 0) atomicAdd(&g_cnt[curb], cnt);
}

// ---------------- head ----------------
__global__ void head_kernel(const float* __restrict__ Wlin, const float* __restrict__ blin,
                            float* __restrict__ out) {
    int g = threadIdx.x >> 5;
    int lane = threadIdx.x & 31;
    if (g >= GG) return;
    float v = g_pool[g * HH + lane] * Wlin[lane];
#pragma unroll
    for (int o = 16; o > 0; o >>= 1) v += __shfl_xor_sync(0xffffffffu, v, o);
    if (lane == 0) out[g] = v / fmaxf(g_cnt[g], 1.f) + blin[0];
}

// ---------------- launch ----------------
extern "C" void kernel_launch(void* const* d_in, const int* in_sizes, int n_in,
                              void* d_out, int out_size) {
    const float* x     = (const float*)d_in[0];
    const float* ea    = (const float*)d_in[1];
    const void*  eidx  = d_in[2];
    const void*  batch = d_in[3];
    const float *Wn1 = (const float*)d_in[4],  *bn1 = (const float*)d_in[5];
    const float *We1 = (const float*)d_in[6],  *be1 = (const float*)d_in[7],  *att1 = (const float*)d_in[8];
    const float *Wn2 = (const float*)d_in[9],  *bn2 = (const float*)d_in[10];
    const float *We2 = (const float*)d_in[11], *be2 = (const float*)d_in[12], *att2 = (const float*)d_in[13];
    const float *Wn3 = (const float*)d_in[14], *bn3 = (const float*)d_in[15];
    const float *We3 = (const float*)d_in[16], *be3 = (const float*)d_in[17], *att3 = (const float*)d_in[18];
    const float *Wlin = (const float*)d_in[19], *blin = (const float*)d_in[20];
    float* out = (float*)d_out;

    const int NODE_BLOCKS = (NN + 255) / 256;
    const int NL_BLOCKS = (NN + 63) / 64;            // 4 threads per node
    const int WARP_BLOCKS = (NN * 32 + 255) / 256;

    deg_prep_kernel<<<(EE / 4 + 255) / 256, 256>>>(eidx,
        We1, be1, att1, We2, be2, att2, We3, be3, att3);
    scanA_kernel<<<NB, 1024>>>();
    scanC_kernel<<<NB, 1024>>>();
    scatter_fused_kernel<<<(EE / 2 + 255) / 256, 256>>>(eidx, ea);

    // layer 1
    node_linear_kernel<16, false, false><<<NL_BLOCKS, 256>>>(x, Wn1, bn1, att1);
    edge_fused_kernel<0><<<WARP_BLOCKS, 256>>>();
    // layer 2
    node_linear_kernel<32, true, true><<<NL_BLOCKS, 256>>>(nullptr, Wn2, bn2, att2);
    edge_fused_kernel<1><<<WARP_BLOCKS, 256>>>();
    // layer 3
    node_linear_kernel<32, true, true><<<NL_BLOCKS, 256>>>(nullptr, Wn3, bn3, att3);
    edge_fused_kernel<2><<<WARP_BLOCKS, 256>>>();

    // pooling + head
    pool_kernel<<<NODE_BLOCKS, 256>>>(batch, (const int*)eidx);
    head_kernel<<<1, 512>>>(Wlin, blin, out);
}

// round 17
// speedup vs baseline: 1.0789x; 1.0306x over previous
#include <cuda_runtime.h>
#include <cuda_fp16.h>

#define NN 50000
#define EE 1600000
#define GG 16
#define HH 32
#define NEG_SLOPE 0.2f
#define NB 49   // scan blocks: ceil(50000/1024)

// ---------------- device scratch (static, no allocs) ----------------
__device__ __align__(128) __half2 g_xnh[NN * 16];   // fp16 node feats (gather target)
__device__ __align__(128) float g_out[NN * HH];     // fp32 layer output / next input
__device__ float g_u[NN];
__device__ float g_v[NN];
__device__ __align__(16) uint2 g_csr[EE];           // {src|et0h<<16, et1h|et2h<<16} grouped by dst
__device__ int   g_deg[NN];                         // zero-initialized; re-zeroed by pool each call
__device__ int   g_rowptr[NN + 1];
__device__ int   g_cursor[NN];
__device__ int   g_bsum[NB];
__device__ __align__(16) float g_w[3][8];
__device__ float g_d[3];
__device__ float g_pool[GG * HH];
__device__ float g_cnt[GG];

// ---------------- per-block dtype sniff: int64 ids have zero high halves ----------------
__device__ __forceinline__ int block_is64(const int* __restrict__ words) {
    __shared__ int sh_is64;
    if (threadIdx.x == 0) {
        int az = 1;
        for (int i = 0; i < 64; i++) {
            if (words[2 * i + 1] != 0) { az = 0; break; }
        }
        sh_is64 = az;
    }
    __syncthreads();
    return sh_is64;
}

// ---------------- deg histogram (4 edges/thread, fire-and-forget REDG) + prep (block 0) ----------------
__global__ void __launch_bounds__(256, 6)
deg_prep_kernel(const void* __restrict__ eidxv,
                const float* We1, const float* be1, const float* att1,
                const float* We2, const float* be2, const float* att2,
                const float* We3, const float* be3, const float* att3) {
    int is64 = block_is64((const int*)eidxv);

    if (blockIdx.x == 0) {
        __shared__ float M2[64], M3[64], c1[8], c2[8], c3[8];
        int t = threadIdx.x;
        if (t < 64) {
            int i = t >> 3, j = t & 7;
            float acc = 0.f;
            for (int k = 0; k < 8; k++) acc += We1[i * 8 + k] * We2[k * 8 + j];
            M2[t] = acc;
            if (i == 0) {
                float c = be2[j];
                for (int k = 0; k < 8; k++) c += be1[k] * We2[k * 8 + j];
                c2[j] = c;
                c1[j] = be1[j];
            }
        }
        __syncthreads();
        if (t < 64) {
            int i = t >> 3, j = t & 7;
            float acc3 = 0.f;
            for (int k = 0; k < 8; k++) acc3 += M2[i * 8 + k] * We3[k * 8 + j];
            M3[t] = acc3;
            if (i == 0) {
                float c = be3[j];
                for (int k = 0; k < 8; k++) c += c2[k] * We3[k * 8 + j];
                c3[j] = c;
            }
        }
        __syncthreads();
        if (t < 24) {
            int l = t >> 3, k = t & 7;
            const float* ae = (l == 0 ? att1 : (l == 1 ? att2 : att3)) + 64;
            float w = 0.f;
            for (int jj = 0; jj < 8; jj++) {
                float m = (l == 0) ? We1[k * 8 + jj] : (l == 1 ? M2[k * 8 + jj] : M3[k * 8 + jj]);
                w += m * ae[jj];
            }
            g_w[l][k] = w;
        }
        if (t < 3) {
            const float* ae = (t == 0 ? att1 : (t == 1 ? att2 : att3)) + 64;
            const float* c = (t == 0 ? c1 : (t == 1 ? c2 : c3));
            float d = 0.f;
            for (int jj = 0; jj < 8; jj++) d += c[jj] * ae[jj];
            g_d[t] = d;
        }
        for (int idx = t; idx < GG * HH; idx += blockDim.x) g_pool[idx] = 0.f;
        if (t < GG) g_cnt[t] = 0.f;
    }

    int t4 = blockIdx.x * blockDim.x + threadIdx.x;
    if (t4 * 4 >= EE) return;
    int d[4];
    if (is64) {
        const longlong4* p = (const longlong4*)((const long long*)eidxv + EE);
        longlong4 q = p[t4];
        d[0] = (int)q.x; d[1] = (int)q.y; d[2] = (int)q.z; d[3] = (int)q.w;
    } else {
        const int4* p = (const int4*)((const int*)eidxv + EE);
        int4 q = p[t4];
        d[0] = q.x; d[1] = q.y; d[2] = q.z; d[3] = q.w;
    }
#pragma unroll
    for (int i = 0; i < 4; i++) {
        int dn = min(max(d[i], 0), NN - 1);
        atomicAdd(&g_deg[dn], 1);   // result unused -> REDG
    }
}

// ---------------- scanA: per-1024-chunk sums ----------------
__global__ void scanA_kernel() {
    __shared__ int sh[32];
    int i = blockIdx.x * 1024 + threadIdx.x;
    int v = (i < NN) ? g_deg[i] : 0;
#pragma unroll
    for (int off = 16; off > 0; off >>= 1) v += __shfl_down_sync(0xffffffffu, v, off);
    if ((threadIdx.x & 31) == 0) sh[threadIdx.x >> 5] = v;
    __syncthreads();
    if (threadIdx.x < 32) {
        int x = sh[threadIdx.x];
#pragma unroll
        for (int off = 16; off > 0; off >>= 1) x += __shfl_down_sync(0xffffffffu, x, off);
        if (threadIdx.x == 0) g_bsum[blockIdx.x] = x;
    }
}

// ---------------- scanC: local scan + inline block-offset reduction ----------------
__global__ void scanC_kernel() {
    __shared__ int wsum[32];
    __shared__ int sred[2];
    int tid = threadIdx.x;
    int lane = tid & 31, wid = tid >> 5;
    if (tid < 64) {
        int v = (tid < blockIdx.x && tid < NB) ? g_bsum[tid] : 0;
#pragma unroll
        for (int off = 16; off > 0; off >>= 1) v += __shfl_down_sync(0xffffffffu, v, off);
        if ((tid & 31) == 0) sred[tid >> 5] = v;
    }
    int i = blockIdx.x * 1024 + tid;
    int v = (i < NN) ? g_deg[i] : 0;
    int incl = v;
#pragma unroll
    for (int off = 1; off < 32; off <<= 1) {
        int x = __shfl_up_sync(0xffffffffu, incl, off);
        if (lane >= off) incl += x;
    }
    if (lane == 31) wsum[wid] = incl;
    __syncthreads();
    if (wid == 0) {
        int x = wsum[lane];
        int xi = x;
#pragma unroll
        for (int off = 1; off < 32; off <<= 1) {
            int y = __shfl_up_sync(0xffffffffu, xi, off);
            if (lane >= off) xi += y;
        }
        wsum[lane] = xi - x;
    }
    __syncthreads();
    int excl = incl - v + wsum[wid] + sred[0] + sred[1];
    if (i < NN) { g_rowptr[i] = excl; g_cursor[i] = excl; }
    if (i == 0) g_rowptr[NN] = EE;
}

// ---------------- fused eterm + scatter: 2 edges/thread, ATOMICS ISSUED FIRST ----------------
// Cursor atomics go out immediately after the index loads so their ~318-cycle
// latency overlaps the ea loads + eterm FMA chain instead of trailing it.
__global__ void __launch_bounds__(256, 6)
scatter_fused_kernel(const void* __restrict__ eidxv, const float* __restrict__ ea) {
    int is64 = block_is64((const int*)eidxv);
    int t = blockIdx.x * blockDim.x + threadIdx.x;
    if (t * 2 >= EE) return;
    int sn[2], dn[2];
    if (is64) {
        const longlong2* ps = (const longlong2*)eidxv;
        const longlong2* pd = (const longlong2*)((const long long*)eidxv + EE);
        longlong2 qs = __ldg(&ps[t]), qd = __ldg(&pd[t]);
        sn[0] = (int)qs.x; sn[1] = (int)qs.y;
        dn[0] = (int)qd.x; dn[1] = (int)qd.y;
    } else {
        const int2* ps = (const int2*)eidxv;
        const int2* pd = (const int2*)((const int*)eidxv + EE);
        int2 qs = __ldg(&ps[t]), qd = __ldg(&pd[t]);
        sn[0] = qs.x; sn[1] = qs.y;
        dn[0] = qd.x; dn[1] = qd.y;
    }
    // cursor atomics FIRST — latency hidden under payload work below
    int pos[2];
#pragma unroll
    for (int k = 0; k < 2; k++) {
        int d = min(max(dn[k], 0), NN - 1);
        pos[k] = atomicAdd(&g_cursor[d], 1);
    }
    const float4* ea4 = (const float4*)ea;
    uint2 pay[2];
#pragma unroll
    for (int k = 0; k < 2; k++) {
        int e = t * 2 + k;
        unsigned s = (unsigned)min(max(sn[k], 0), NN - 1);
        float4 a0 = __ldg(&ea4[e * 2]);
        float4 a1 = __ldg(&ea4[e * 2 + 1]);
        float et[3];
#pragma unroll
        for (int l = 0; l < 3; l++) {
            const float* w = g_w[l];
            et[l] = g_d[l]
                  + a0.x * w[0] + a0.y * w[1] + a0.z * w[2] + a0.w * w[3]
                  + a1.x * w[4] + a1.y * w[5] + a1.z * w[6] + a1.w * w[7];
        }
        unsigned h0 = (unsigned)__half_as_ushort(__float2half_rn(et[0]));
        unsigned h1 = (unsigned)__half_as_ushort(__float2half_rn(et[1]));
        unsigned h2 = (unsigned)__half_as_ushort(__float2half_rn(et[2]));
        pay[k].x = s | (h0 << 16);
        pay[k].y = h1 | (h2 << 16);
    }
#pragma unroll
    for (int k = 0; k < 2; k++) g_csr[pos[k]] = pay[k];
}

// ---------------- node linear: smem-staged input, fp16 xn output (R12-verified) ----------------
template <int IN, bool RELU, bool FROM_GOUT>
__global__ void node_linear_kernel(const float* __restrict__ xin_ext,
                                   const float* __restrict__ W,
                                   const float* __restrict__ b,
                                   const float* __restrict__ att) {
    __shared__ float sW[IN * HH];
    __shared__ float sb[HH];
    __shared__ float sA[64];
    __shared__ float sX[256 * (IN + 1)];
    int tid = threadIdx.x;
    for (int i = tid; i < IN * HH; i += blockDim.x) sW[i] = W[i];
    if (tid < HH) sb[tid] = b[tid];
    if (tid < 64) sA[tid] = att[tid];
    int base = blockIdx.x * 256;
    int nvalid = min(256, NN - base);
    const float* src = FROM_GOUT ? g_out : xin_ext;
    for (int i = tid; i < nvalid * IN; i += 256) {
        int nl = i / IN;
        int k = i - nl * IN;
        sX[nl * (IN + 1) + k] = src[(size_t)base * IN + i];
    }
    __syncthreads();
    int node = base + tid;
    if (tid >= nvalid) return;
    const float* xr = sX + tid * (IN + 1);
    float acc[HH];
#pragma unroll
    for (int h = 0; h < HH; h++) acc[h] = sb[h];
#pragma unroll
    for (int k = 0; k < IN; k++) {
        float xv = xr[k];
        if (RELU) xv = fmaxf(xv, 0.f);
#pragma unroll
        for (int h = 0; h < HH; h++) acc[h] = fmaf(xv, sW[k * HH + h], acc[h]);
    }
    uint4* o = (uint4*)(g_xnh + (size_t)node * 16);
#pragma unroll
    for (int q = 0; q < 4; q++) {
        uint4 pk;
        __half2 h0 = __floats2half2_rn(acc[8 * q + 0], acc[8 * q + 1]);
        __half2 h1 = __floats2half2_rn(acc[8 * q + 2], acc[8 * q + 3]);
        __half2 h2 = __floats2half2_rn(acc[8 * q + 4], acc[8 * q + 5]);
        __half2 h3 = __floats2half2_rn(acc[8 * q + 6], acc[8 * q + 7]);
        pk.x = *(unsigned*)&h0; pk.y = *(unsigned*)&h1;
        pk.z = *(unsigned*)&h2; pk.w = *(unsigned*)&h3;
        o[q] = pk;
    }
    float u = 0.f, v = 0.f;
#pragma unroll
    for (int h = 0; h < HH; h++) {
        u = fmaf(acc[h], sA[h], u);
        v = fmaf(acc[h], sA[h + 32], v);
    }
    g_u[node] = u;
    g_v[node] = v;
}

// ---------------- fused softmax + aggregate: one warp per dst node ----------------
// Phase 1: 32 lanes compute p for 32 edges, stage {sn,p} in smem.
// Phase 2: 4-deep prefetch — load all 4 row-slices per 4-lane group, then FMA.
// All read-only global traffic via __ldg.
template <int L>
__global__ void edge_fused_kernel() {
    __shared__ __align__(8) float2 sE[8][32];
    int wib = threadIdx.x >> 5;
    int w = (blockIdx.x * blockDim.x + threadIdx.x) >> 5;
    int lane = threadIdx.x & 31;
    if (w >= NN) return;
    int start = __ldg(&g_rowptr[w]);
    int end = __ldg(&g_rowptr[w + 1]);
    float u = __ldg(&g_u[w]);
    int part = lane & 3, grp = lane >> 2;
    float acc[8] = {0.f, 0.f, 0.f, 0.f, 0.f, 0.f, 0.f, 0.f};
    float s = 0.f;
    for (int base = start; base < end; base += 32) {
        int e = base + lane;
        float p = 0.f; int sn = 0;
        if (e < end) {
            uint2 q = __ldg(&g_csr[e]);
            sn = (int)(q.x & 0xffffu);
            unsigned hb = (L == 0) ? (q.x >> 16) : (L == 1) ? (q.y & 0xffffu) : (q.y >> 16);
            float et = __half2float(__ushort_as_half((unsigned short)hb));
            float lg = u + __ldg(&g_v[sn]) + et;
            lg = (lg > 0.f) ? lg : NEG_SLOPE * lg;
            p = __expf(lg);
        }
        sE[wib][lane] = make_float2(__int_as_float(sn), p);
        __syncwarp();
        int cnt = min(32, end - base);
        float pj[4];
        uint4 rvj[4];
#pragma unroll
        for (int it = 0; it < 4; it++) {
            int j = grp + it * 8;
            if (j < cnt) {
                float2 sp = sE[wib][j];
                pj[it] = sp.y;
                rvj[it] = __ldg(((const uint4*)(g_xnh + (size_t)__float_as_int(sp.x) * 16)) + part);
            } else {
                pj[it] = 0.f;
                rvj[it] = make_uint4(0u, 0u, 0u, 0u);
            }
        }
#pragma unroll
        for (int it = 0; it < 4; it++) {
            float pp = pj[it];
            uint4 rv = rvj[it];
            float2 f0 = __half22float2(*(__half2*)&rv.x);
            float2 f1 = __half22float2(*(__half2*)&rv.y);
            float2 f2 = __half22float2(*(__half2*)&rv.z);
            float2 f3 = __half22float2(*(__half2*)&rv.w);
            acc[0] = fmaf(pp, f0.x, acc[0]);
            acc[1] = fmaf(pp, f0.y, acc[1]);
            acc[2] = fmaf(pp, f1.x, acc[2]);
            acc[3] = fmaf(pp, f1.y, acc[3]);
            acc[4] = fmaf(pp, f2.x, acc[4]);
            acc[5] = fmaf(pp, f2.y, acc[5]);
            acc[6] = fmaf(pp, f3.x, acc[6]);
            acc[7] = fmaf(pp, f3.y, acc[7]);
            s += pp;
        }
        __syncwarp();
    }
#pragma unroll
    for (int off = 16; off >= 4; off >>= 1) {
#pragma unroll
        for (int i = 0; i < 8; i++) acc[i] += __shfl_down_sync(0xffffffffu, acc[i], off);
        s += __shfl_down_sync(0xffffffffu, s, off);
    }
    if (grp == 0) {
        float inv = 1.f / (s + 1e-16f);
        float4* o = (float4*)(g_out + (size_t)w * HH);
        o[part * 2]     = make_float4(acc[0] * inv, acc[1] * inv, acc[2] * inv, acc[3] * inv);
        o[part * 2 + 1] = make_float4(acc[4] * inv, acc[5] * inv, acc[6] * inv, acc[7] * inv);
    }
}

// ---------------- mean pool over sorted batch; re-zero g_deg for next call ----------------
__global__ void pool_kernel(const void* __restrict__ batchv, const int* __restrict__ eidx_words) {
    int is64 = block_is64(eidx_words);
    int gtid = blockIdx.x * blockDim.x + threadIdx.x;
    if (gtid < NN) g_deg[gtid] = 0;
    int w = gtid >> 5;
    int lane = threadIdx.x & 31;
    int base = w * 32;
    if (base >= NN) return;
    int nmax = min(32, NN - base);
    int myb = 0;
    if (lane < nmax) {
        if (is64) myb = (int)((const long long*)batchv)[base + lane];
        else      myb = ((const int*)batchv)[base + lane];
        myb = min(max(myb, 0), GG - 1);
    }
    float acc = 0.f, cnt = 0.f;
    int curb = __shfl_sync(0xffffffffu, myb, 0);
    for (int n = 0; n < nmax; n++) {
        int b = __shfl_sync(0xffffffffu, myb, n);
        if (b != curb) {
            atomicAdd(&g_pool[curb * HH + lane], acc);
            if (lane == 0) atomicAdd(&g_cnt[curb], cnt);
            acc = 0.f; cnt = 0.f; curb = b;
        }
        acc += g_out[(size_t)(base + n) * HH + lane];
        cnt += 1.f;
    }
    atomicAdd(&g_pool[curb * HH + lane], acc);
    if (lane == 0) atomicAdd(&g_cnt[curb], cnt);
}

// ---------------- head ----------------
__global__ void head_kernel(const float* __restrict__ Wlin, const float* __restrict__ blin,
                            float* __restrict__ out) {
    int g = threadIdx.x >> 5;
    int lane = threadIdx.x & 31;
    if (g >= GG) return;
    float v = g_pool[g * HH + lane] * Wlin[lane];
#pragma unroll
    for (int o = 16; o > 0; o >>= 1) v += __shfl_xor_sync(0xffffffffu, v, o);
    if (lane == 0) out[g] = v / fmaxf(g_cnt[g], 1.f) + blin[0];
}

// ---------------- launch ----------------
extern "C" void kernel_launch(void* const* d_in, const int* in_sizes, int n_in,
                              void* d_out, int out_size) {
    const float* x     = (const float*)d_in[0];
    const float* ea    = (const float*)d_in[1];
    const void*  eidx  = d_in[2];
    const void*  batch = d_in[3];
    const float *Wn1 = (const float*)d_in[4],  *bn1 = (const float*)d_in[5];
    const float *We1 = (const float*)d_in[6],  *be1 = (const float*)d_in[7],  *att1 = (const float*)d_in[8];
    const float *Wn2 = (const float*)d_in[9],  *bn2 = (const float*)d_in[10];
    const float *We2 = (const float*)d_in[11], *be2 = (const float*)d_in[12], *att2 = (const float*)d_in[13];
    const float *Wn3 = (const float*)d_in[14], *bn3 = (const float*)d_in[15];
    const float *We3 = (const float*)d_in[16], *be3 = (const float*)d_in[17], *att3 = (const float*)d_in[18];
    const float *Wlin = (const float*)d_in[19], *blin = (const float*)d_in[20];
    float* out = (float*)d_out;

    const int NODE_BLOCKS = (NN + 255) / 256;
    const int WARP_BLOCKS = (NN * 32 + 255) / 256;

    deg_prep_kernel<<<(EE / 4 + 255) / 256, 256>>>(eidx,
        We1, be1, att1, We2, be2, att2, We3, be3, att3);
    scanA_kernel<<<NB, 1024>>>();
    scanC_kernel<<<NB, 1024>>>();
    scatter_fused_kernel<<<(EE / 2 + 255) / 256, 256>>>(eidx, ea);

    // layer 1
    node_linear_kernel<16, false, false><<<NODE_BLOCKS, 256>>>(x, Wn1, bn1, att1);
    edge_fused_kernel<0><<<WARP_BLOCKS, 256>>>();
    // layer 2
    node_linear_kernel<32, true, true><<<NODE_BLOCKS, 256>>>(nullptr, Wn2, bn2, att2);
    edge_fused_kernel<1><<<WARP_BLOCKS, 256>>>();
    // layer 3
    node_linear_kernel<32, true, true><<<NODE_BLOCKS, 256>>>(nullptr, Wn3, bn3, att3);
    edge_fused_kernel<2><<<WARP_BLOCKS, 256>>>();

    // pooling + head
    pool_kernel<<<NODE_BLOCKS, 256>>>(batch, (const int*)eidx);
    head_kernel<<<1, 512>>>(Wlin, blin, out);
}